// round 1
// baseline (speedup 1.0000x reference)
#include <cuda_runtime.h>
#include <cuda_fp8.h>
#include <cuda_fp16.h>

#define T_ 512
#define D_ 2048
#define I_ 768
#define E_ 16
#define K_ 8

// ---------------- scratch (device globals; no allocations allowed) ----------
__device__ float g_xq[T_ * D_];            // 4 MB   quant-dequant activations
__device__ int   g_tok[E_ * T_];           // token index per (expert, slot)
__device__ float g_wt[E_ * T_];            // combined routing weight per slot
__device__ int   g_cnt[E_];                // tokens per expert
__device__ int   g_slot[T_ * E_];          // (token, expert) -> slot or -1
__device__ float g_act[E_ * T_ * I_];      // 25 MB  silu(gate)*up
__device__ float g_y[E_ * T_ * D_];        // 64 MB  per-expert weighted outputs

__constant__ float c_fp4[16] = {0.f, 0.5f, 1.f, 1.5f, 2.f, 3.f, 4.f, 6.f,
                                -0.f, -0.5f, -1.f, -1.5f, -2.f, -3.f, -4.f, -6.f};

// ---------------- 1) fp8 quant-dequant (group = 32, one warp per group) -----
__global__ __launch_bounds__(256) void k_quant(const float* __restrict__ x) {
    int g    = blockIdx.x * 8 + (threadIdx.x >> 5);
    int lane = threadIdx.x & 31;
    int idx  = g * 32 + lane;
    float v  = x[idx];
    float a  = fabsf(v);
#pragma unroll
    for (int s = 16; s; s >>= 1) a = fmaxf(a, __shfl_xor_sync(0xffffffffu, a, s));
    a = fmaxf(a, 1e-4f);
    float scale   = __fdiv_rn(a, 448.0f);                 // exact RN divide (match ref)
    unsigned bits = __float_as_uint(scale);
    unsigned ex   = ((bits >> 23) & 255u) + ((bits & 0x7fffffu) ? 1u : 0u);
    ex = ex < 1u ? 1u : (ex > 254u ? 254u : ex);
    float rscale = __uint_as_float(ex << 23);             // 2^(ex-127)
    float rinv   = __uint_as_float((254u - ex) << 23);    // exact reciprocal (pow2)
    float q      = v * rinv;
    __nv_fp8_storage_t f8 = __nv_cvt_float_to_fp8(q, __NV_SATFINITE, __NV_E4M3);
    __half_raw hr = __nv_cvt_fp8_to_halfraw(f8, __NV_E4M3);
    g_xq[idx] = __half2float(__half(hr)) * rscale;
}

// ---------------- 2) routing compaction (single block, deterministic) -------
__global__ __launch_bounds__(512) void k_route(const float* __restrict__ tw,
                                               const int* __restrict__ tids) {
    __shared__ int s_cnt[E_];
    int t = threadIdx.x;
    if (t < E_) s_cnt[t] = 0;
    __syncthreads();

    float w[K_]; int id[K_];
#pragma unroll
    for (int k = 0; k < K_; k++) { w[k] = tw[t * K_ + k]; id[k] = tids[t * K_ + k]; }

    for (int e = 0; e < E_; e++) {
        float c = 0.f;
#pragma unroll
        for (int k = 0; k < K_; k++) if (id[k] == e) c += w[k];
        int slot = -1;
        if (c > 0.f) {
            slot = atomicAdd(&s_cnt[e], 1);
            g_tok[e * T_ + slot] = t;
            g_wt[e * T_ + slot]  = c;
        }
        g_slot[t * E_ + e] = slot;
    }
    __syncthreads();
    if (t < E_) g_cnt[t] = s_cnt[t];
}

// ---------------- 3) GEMM1: h = X @ w13^T, fused silu(gate)*up --------------
// block tile: 64 tokens x (64 gate feats + 64 up feats), BK = 32 over D
__global__ __launch_bounds__(256) void k_gemm1(const int* __restrict__ w13,
                                               const int* __restrict__ w13s) {
    const int e   = blockIdx.z;
    const int cnt = g_cnt[e];
    const int m0  = blockIdx.y * 64;
    if (m0 >= cnt) return;
    const int n0  = blockIdx.x * 64;

    __shared__ float xs[32][65];   // [k][m], +1 pad => conflict-free transpose store
    __shared__ float wg[32][64];   // [k][n] gate
    __shared__ float wu[32][64];   // [k][n] up
    __shared__ int   toks[64];

    const int tid = threadIdx.x;
    if (tid < 64) {
        int m = m0 + tid;
        toks[tid] = (m < cnt) ? g_tok[e * T_ + m] : -1;
    }
    __syncthreads();

    float accG[4][4] = {}, accU[4][4] = {};
    const int ty = tid >> 4, tx = tid & 15;

    const int xm   = tid >> 2;             // 0..63 token row
    const int xk   = (tid & 3) * 8;        // k sub-chunk
    const int tokm = toks[xm];

    const int wr    = tid >> 1;            // 0..127 weight row
    const int wIsUp = wr >> 6;
    const int wn    = wr & 63;
    const int wf    = wIsUp ? (I_ + n0 + wn) : (n0 + wn);
    const int wb    = (tid & 1) * 8;       // packed-word sub-chunk
    const int* wrow = w13  + (e * (2 * I_) + wf) * (D_ / 2);
    const int* srow = w13s + (e * (2 * I_) + wf) * (D_ / 32);
    float* wdst = wIsUp ? &wu[0][0] : &wg[0][0];

    for (int k0 = 0; k0 < D_; k0 += 32) {
        // X tile (transpose into [k][m])
        if (tokm >= 0) {
            const float* xp = g_xq + tokm * D_ + k0 + xk;
            float4 v0 = *(const float4*)xp;
            float4 v1 = *(const float4*)(xp + 4);
            xs[xk+0][xm] = v0.x; xs[xk+1][xm] = v0.y; xs[xk+2][xm] = v0.z; xs[xk+3][xm] = v0.w;
            xs[xk+4][xm] = v1.x; xs[xk+5][xm] = v1.y; xs[xk+6][xm] = v1.z; xs[xk+7][xm] = v1.w;
        } else {
#pragma unroll
            for (int j = 0; j < 8; j++) xs[xk + j][xm] = 0.f;
        }
        // W tiles: dequant MXFP4 on the fly (8 packed words -> 16 floats)
        {
            float s = __uint_as_float(((unsigned)srow[k0 >> 5]) << 23);
            const int* wp = wrow + (k0 >> 1) + wb;
#pragma unroll
            for (int j = 0; j < 8; j++) {
                int wv = wp[j];
                int kk = (wb + j) * 2;
                wdst[kk * 64 + wn]       = c_fp4[wv & 15] * s;
                wdst[(kk + 1) * 64 + wn] = c_fp4[(wv >> 4) & 15] * s;
            }
        }
        __syncthreads();
#pragma unroll 8
        for (int k = 0; k < 32; k++) {
            float a[4];
#pragma unroll
            for (int i = 0; i < 4; i++) a[i] = xs[k][ty * 4 + i];
            float4 bg4 = *(const float4*)&wg[k][tx * 4];
            float4 bu4 = *(const float4*)&wu[k][tx * 4];
            float bg[4] = {bg4.x, bg4.y, bg4.z, bg4.w};
            float bu[4] = {bu4.x, bu4.y, bu4.z, bu4.w};
#pragma unroll
            for (int i = 0; i < 4; i++)
#pragma unroll
                for (int j = 0; j < 4; j++) {
                    accG[i][j] = fmaf(a[i], bg[j], accG[i][j]);
                    accU[i][j] = fmaf(a[i], bu[j], accU[i][j]);
                }
        }
        __syncthreads();
    }
    // epilogue: silu(gate) * up
#pragma unroll
    for (int i = 0; i < 4; i++) {
        int m = m0 + ty * 4 + i;
        if (m < cnt) {
            float* arow = g_act + (e * T_ + m) * I_ + n0 + tx * 4;
#pragma unroll
            for (int j = 0; j < 4; j++) {
                float g = accG[i][j], u = accU[i][j];
                float sig = 1.f / (1.f + expf(-g));
                arow[j] = g * sig * u;
            }
        }
    }
}

// ---------------- 4) GEMM2: y = a @ w2^T, comb weight folded into store -----
__global__ __launch_bounds__(256) void k_gemm2(const int* __restrict__ w2,
                                               const int* __restrict__ w2s) {
    const int e   = blockIdx.z;
    const int cnt = g_cnt[e];
    const int m0  = blockIdx.y * 64;
    if (m0 >= cnt) return;
    const int n0  = blockIdx.x * 64;   // output d base

    __shared__ float as_[32][65];
    __shared__ float ws[32][64];

    const int tid = threadIdx.x;
    const int ty = tid >> 4, tx = tid & 15;

    const int xm = tid >> 2;
    const int xk = (tid & 3) * 8;
    const int arow_ok = (m0 + xm) < cnt;
    const float* arow = g_act + (e * T_ + m0 + xm) * I_;

    const int wrn = tid >> 2;          // 0..63 (d row within tile)
    const int wb  = (tid & 3) * 4;     // packed-word sub-chunk
    const int* wrow = w2  + (e * D_ + n0 + wrn) * (I_ / 2);
    const int* srow = w2s + (e * D_ + n0 + wrn) * (I_ / 32);

    float acc[4][4] = {};

    for (int k0 = 0; k0 < I_; k0 += 32) {
        if (arow_ok) {
            float4 v0 = *(const float4*)(arow + k0 + xk);
            float4 v1 = *(const float4*)(arow + k0 + xk + 4);
            as_[xk+0][xm] = v0.x; as_[xk+1][xm] = v0.y; as_[xk+2][xm] = v0.z; as_[xk+3][xm] = v0.w;
            as_[xk+4][xm] = v1.x; as_[xk+5][xm] = v1.y; as_[xk+6][xm] = v1.z; as_[xk+7][xm] = v1.w;
        } else {
#pragma unroll
            for (int j = 0; j < 8; j++) as_[xk + j][xm] = 0.f;
        }
        {
            float s = __uint_as_float(((unsigned)srow[k0 >> 5]) << 23);
            const int* wp = wrow + (k0 >> 1) + wb;
#pragma unroll
            for (int j = 0; j < 4; j++) {
                int wv = wp[j];
                int kk = (wb + j) * 2;
                ws[kk][wrn]     = c_fp4[wv & 15] * s;
                ws[kk + 1][wrn] = c_fp4[(wv >> 4) & 15] * s;
            }
        }
        __syncthreads();
#pragma unroll 8
        for (int k = 0; k < 32; k++) {
            float a[4];
#pragma unroll
            for (int i = 0; i < 4; i++) a[i] = as_[k][ty * 4 + i];
            float4 b4 = *(const float4*)&ws[k][tx * 4];
            float b[4] = {b4.x, b4.y, b4.z, b4.w};
#pragma unroll
            for (int i = 0; i < 4; i++)
#pragma unroll
                for (int j = 0; j < 4; j++)
                    acc[i][j] = fmaf(a[i], b[j], acc[i][j]);
        }
        __syncthreads();
    }
#pragma unroll
    for (int i = 0; i < 4; i++) {
        int m = m0 + ty * 4 + i;
        if (m < cnt) {
            float wc = g_wt[e * T_ + m];
            float* yrow = g_y + (e * T_ + m) * D_ + n0 + tx * 4;
#pragma unroll
            for (int j = 0; j < 4; j++) yrow[j] = acc[i][j] * wc;
        }
    }
}

// ---------------- 5) combine: out[t,d] = sum_e y[e, slot(t,e), d] -----------
__global__ __launch_bounds__(256) void k_combine(float* __restrict__ out) {
    int t = blockIdx.x;
    __shared__ int sl[E_];
    if (threadIdx.x < E_) sl[threadIdx.x] = g_slot[t * E_ + threadIdx.x];
    __syncthreads();
    for (int d = threadIdx.x; d < D_; d += 256) {
        float acc = 0.f;
#pragma unroll
        for (int e = 0; e < E_; e++) {
            int s = sl[e];
            if (s >= 0) acc += g_y[(e * T_ + s) * D_ + d];
        }
        out[t * D_ + d] = acc;
    }
}

// ---------------- launch -----------------------------------------------------
extern "C" void kernel_launch(void* const* d_in, const int* in_sizes, int n_in,
                              void* d_out, int out_size) {
    const float* x    = (const float*)d_in[0];
    const float* tw   = (const float*)d_in[1];
    const int*   tids = (const int*)d_in[2];
    const int*   w13  = (const int*)d_in[3];
    const int*   w13s = (const int*)d_in[4];
    const int*   w2   = (const int*)d_in[5];
    const int*   w2s  = (const int*)d_in[6];
    float* out = (float*)d_out;

    k_quant<<<(T_ * D_ / 32) / 8, 256>>>(x);
    k_route<<<1, 512>>>(tw, tids);
    k_gemm1<<<dim3(I_ / 64, T_ / 64, E_), 256>>>(w13, w13s);
    k_gemm2<<<dim3(D_ / 64, T_ / 64, E_), 256>>>(w2, w2s);
    k_combine<<<T_, 256>>>(out);
}

// round 2
// speedup vs baseline: 3.6106x; 3.6106x over previous
#include <cuda_runtime.h>
#include <cuda_fp8.h>
#include <cuda_fp16.h>

#define T_ 512
#define D_ 2048
#define I_ 768
#define E_ 16
#define K_ 8
#define H2_ 1536   // 2*I

// ---------------- scratch (device globals; no allocations allowed) ----------
__device__ __half g_xqh[T_ * D_];          // 2 MB   quant-dequant activations (fp16, exact)
__device__ int    g_tok[E_ * T_];          // token index per (expert, slot)
__device__ float  g_wt[E_ * T_];           // combined routing weight per slot
__device__ int    g_cnt[E_];               // tokens per expert
__device__ int    g_slot[T_ * E_];         // (token, expert) -> slot or -1
__device__ float  g_h[E_ * T_ * H2_];      // 50 MB  gemm1 output (gate|up)
__device__ __half g_acth[E_ * T_ * I_];    // 12.6MB silu(gate)*up (fp16)
__device__ float  g_y[E_ * T_ * D_];       // 64 MB  per-expert weighted outputs

// fp4 e2m1 nibble -> float, pure ALU decode
__device__ __forceinline__ float fp4f(unsigned nib) {
    unsigned e = (nib >> 1) & 3u, m = nib & 1u, s = (nib & 8u) << 28;
    unsigned bits = e ? (((e + 126u) << 23) | (m << 22)) : (m ? 0x3F000000u : 0u);
    return __uint_as_float(bits | s);
}

__device__ __forceinline__ void mma16816(float* c, const unsigned* a, const unsigned* b) {
    asm volatile(
        "mma.sync.aligned.m16n8k16.row.col.f32.f16.f16.f32 "
        "{%0,%1,%2,%3}, {%4,%5,%6,%7}, {%8,%9}, {%0,%1,%2,%3};\n"
        : "+f"(c[0]), "+f"(c[1]), "+f"(c[2]), "+f"(c[3])
        : "r"(a[0]), "r"(a[1]), "r"(a[2]), "r"(a[3]), "r"(b[0]), "r"(b[1]));
}

// ---------------- 1) fp8 quant-dequant (group = 32, one warp per group) -----
__global__ __launch_bounds__(256) void k_quant(const float* __restrict__ x) {
    int g    = blockIdx.x * 8 + (threadIdx.x >> 5);
    int lane = threadIdx.x & 31;
    int idx  = g * 32 + lane;
    float v  = x[idx];
    float a  = fabsf(v);
#pragma unroll
    for (int s = 16; s; s >>= 1) a = fmaxf(a, __shfl_xor_sync(0xffffffffu, a, s));
    a = fmaxf(a, 1e-4f);
    float scale   = __fdiv_rn(a, 448.0f);
    unsigned bits = __float_as_uint(scale);
    unsigned ex   = ((bits >> 23) & 255u) + ((bits & 0x7fffffu) ? 1u : 0u);
    ex = ex < 1u ? 1u : (ex > 254u ? 254u : ex);
    float rscale = __uint_as_float(ex << 23);
    float rinv   = __uint_as_float((254u - ex) << 23);
    float q      = v * rinv;
    __nv_fp8_storage_t f8 = __nv_cvt_float_to_fp8(q, __NV_SATFINITE, __NV_E4M3);
    __half_raw hr = __nv_cvt_fp8_to_halfraw(f8, __NV_E4M3);
    g_xqh[idx] = __float2half(__half2float(__half(hr)) * rscale);
}

// ---------------- 2) routing compaction (single block, deterministic) -------
__global__ __launch_bounds__(512) void k_route(const float* __restrict__ tw,
                                               const int* __restrict__ tids) {
    __shared__ int s_cnt[E_];
    int t = threadIdx.x;
    if (t < E_) s_cnt[t] = 0;
    __syncthreads();
    float w[K_]; int id[K_];
#pragma unroll
    for (int k = 0; k < K_; k++) { w[k] = tw[t * K_ + k]; id[k] = tids[t * K_ + k]; }
    for (int e = 0; e < E_; e++) {
        float c = 0.f;
#pragma unroll
        for (int k = 0; k < K_; k++) if (id[k] == e) c += w[k];
        int slot = -1;
        if (c > 0.f) {
            slot = atomicAdd(&s_cnt[e], 1);
            g_tok[e * T_ + slot] = t;
            g_wt[e * T_ + slot]  = c;
        }
        g_slot[t * E_ + e] = slot;
    }
    __syncthreads();
    if (t < E_) g_cnt[t] = s_cnt[t];
}

// ---------------- 3) GEMM1: g_h = X @ w13^T (64M x 128N x BK32, HMMA) -------
__global__ __launch_bounds__(256) void k_gemm1(const int* __restrict__ w13,
                                               const int* __restrict__ w13s) {
    const int e   = blockIdx.z;
    const int cnt = g_cnt[e];
    const int m0  = blockIdx.y * 64;
    if (m0 >= cnt) return;
    const int n0  = blockIdx.x * 128;

    __shared__ __half as_[64][40];   // [m][k], 80B row stride (conflict-free)
    __shared__ __half ws[128][40];   // [n][k]
    __shared__ int    toks[64];

    const int tid  = threadIdx.x;
    const int lane = tid & 31;
    const int w    = tid >> 5;
    const int mw   = (w >> 2) * 32;  // warp m offset
    const int nw   = (w & 3) * 32;   // warp n offset

    if (tid < 64) {
        int m = m0 + tid;
        toks[tid] = (m < cnt) ? g_tok[e * T_ + m] : -1;
    }
    __syncthreads();

    // A fill mapping
    const int ar = tid >> 2;             // 0..63
    const int ac = (tid & 3) * 8;        // k sub-chunk (8 halves = 16B)
    const int tok = toks[ar];
    const __half* arow_g = g_xqh + (tok >= 0 ? tok : 0) * D_;

    // B fill mapping: 128 rows x 16 words per k0; 2 threads/row
    const int wr = tid >> 1;             // 0..127
    const int wb = (tid & 1) * 8;        // word sub-chunk
    const int f  = n0 + wr;
    const int* wrow = w13  + (e * H2_ + f) * (D_ / 2);
    const int* srow = w13s + (e * H2_ + f) * (D_ / 32);

    float acc[2][4][4] = {};

    for (int k0 = 0; k0 < D_; k0 += 32) {
        // A tile
        if (tok >= 0) {
            uint4 v = *(const uint4*)(arow_g + k0 + ac);
            *(uint4*)&as_[ar][ac] = v;
        } else {
            *(uint4*)&as_[ar][ac] = make_uint4(0, 0, 0, 0);
        }
        // B tile: dequant 8 packed words -> 16 fp16
        {
            float s = __uint_as_float(((unsigned)srow[k0 >> 5]) << 23);
            const int* wp = wrow + (k0 >> 1) + wb;
            int4 wv0 = *(const int4*)wp;
            int4 wv1 = *(const int4*)(wp + 4);
            int wvs[8] = {wv0.x, wv0.y, wv0.z, wv0.w, wv1.x, wv1.y, wv1.z, wv1.w};
#pragma unroll
            for (int j = 0; j < 8; j++) {
                int wv = wvs[j];
                float lo = fp4f(wv & 15) * s;
                float hi = fp4f((wv >> 4) & 15) * s;
                *(__half2*)&ws[wr][(wb + j) * 2] = __floats2half2_rn(lo, hi);
            }
        }
        __syncthreads();
#pragma unroll
        for (int ks = 0; ks < 2; ks++) {
            const int kc = ks * 16 + (lane & 3) * 2;
            const int r0 = lane >> 2;
            unsigned af[2][4];
#pragma unroll
            for (int mi = 0; mi < 2; mi++) {
                int rb = mw + mi * 16 + r0;
                af[mi][0] = *(const unsigned*)&as_[rb][kc];
                af[mi][1] = *(const unsigned*)&as_[rb + 8][kc];
                af[mi][2] = *(const unsigned*)&as_[rb][kc + 8];
                af[mi][3] = *(const unsigned*)&as_[rb + 8][kc + 8];
            }
#pragma unroll
            for (int nj = 0; nj < 4; nj++) {
                int bn = nw + nj * 8 + r0;
                unsigned bf[2];
                bf[0] = *(const unsigned*)&ws[bn][kc];
                bf[1] = *(const unsigned*)&ws[bn][kc + 8];
                mma16816(acc[0][nj], af[0], bf);
                mma16816(acc[1][nj], af[1], bf);
            }
        }
        __syncthreads();
    }
    // epilogue: write fp32 h
#pragma unroll
    for (int mi = 0; mi < 2; mi++) {
#pragma unroll
        for (int nj = 0; nj < 4; nj++) {
            int row = mw + mi * 16 + (lane >> 2);
            int col = n0 + nw + nj * 8 + (lane & 3) * 2;
            int m0r = m0 + row;
            if (m0r < cnt) {
                float* hp = g_h + (e * T_ + m0r) * H2_ + col;
                hp[0] = acc[mi][nj][0];
                hp[1] = acc[mi][nj][1];
            }
            if (m0r + 8 < cnt) {
                float* hp = g_h + (e * T_ + m0r + 8) * H2_ + col;
                hp[0] = acc[mi][nj][2];
                hp[1] = acc[mi][nj][3];
            }
        }
    }
}

// ---------------- 3b) activation: a = silu(gate) * up -> fp16 ---------------
__global__ __launch_bounds__(256) void k_act() {
    int e = blockIdx.y;
    int m = blockIdx.x;
    if (m >= g_cnt[e]) return;
    const float* hrow = g_h + (e * T_ + m) * H2_;
    __half* arow = g_acth + (e * T_ + m) * I_;
    for (int i = threadIdx.x; i < I_; i += 256) {
        float g = hrow[i], u = hrow[i + I_];
        float sig = 1.f / (1.f + expf(-g));
        arow[i] = __float2half(g * sig * u);
    }
}

// ---------------- 4) GEMM2: y = a @ w2^T (64M x 128N x BK32, HMMA) ----------
__global__ __launch_bounds__(256) void k_gemm2(const int* __restrict__ w2,
                                               const int* __restrict__ w2s) {
    const int e   = blockIdx.z;
    const int cnt = g_cnt[e];
    const int m0  = blockIdx.y * 64;
    if (m0 >= cnt) return;
    const int n0  = blockIdx.x * 128;

    __shared__ __half as_[64][40];
    __shared__ __half ws[128][40];

    const int tid  = threadIdx.x;
    const int lane = tid & 31;
    const int w    = tid >> 5;
    const int mw   = (w >> 2) * 32;
    const int nw   = (w & 3) * 32;

    const int ar = tid >> 2;
    const int ac = (tid & 3) * 8;
    const int arow_ok = (m0 + ar) < cnt;
    const __half* arow_g = g_acth + (e * T_ + (arow_ok ? m0 + ar : 0)) * I_;

    const int wr = tid >> 1;
    const int wb = (tid & 1) * 8;
    const int dd = n0 + wr;
    const int* wrow = w2  + (e * D_ + dd) * (I_ / 2);
    const int* srow = w2s + (e * D_ + dd) * (I_ / 32);

    float acc[2][4][4] = {};

    for (int k0 = 0; k0 < I_; k0 += 32) {
        if (arow_ok) {
            uint4 v = *(const uint4*)(arow_g + k0 + ac);
            *(uint4*)&as_[ar][ac] = v;
        } else {
            *(uint4*)&as_[ar][ac] = make_uint4(0, 0, 0, 0);
        }
        {
            float s = __uint_as_float(((unsigned)srow[k0 >> 5]) << 23);
            const int* wp = wrow + (k0 >> 1) + wb;
            int4 wv0 = *(const int4*)wp;
            int4 wv1 = *(const int4*)(wp + 4);
            int wvs[8] = {wv0.x, wv0.y, wv0.z, wv0.w, wv1.x, wv1.y, wv1.z, wv1.w};
#pragma unroll
            for (int j = 0; j < 8; j++) {
                int wv = wvs[j];
                float lo = fp4f(wv & 15) * s;
                float hi = fp4f((wv >> 4) & 15) * s;
                *(__half2*)&ws[wr][(wb + j) * 2] = __floats2half2_rn(lo, hi);
            }
        }
        __syncthreads();
#pragma unroll
        for (int ks = 0; ks < 2; ks++) {
            const int kc = ks * 16 + (lane & 3) * 2;
            const int r0 = lane >> 2;
            unsigned af[2][4];
#pragma unroll
            for (int mi = 0; mi < 2; mi++) {
                int rb = mw + mi * 16 + r0;
                af[mi][0] = *(const unsigned*)&as_[rb][kc];
                af[mi][1] = *(const unsigned*)&as_[rb + 8][kc];
                af[mi][2] = *(const unsigned*)&as_[rb][kc + 8];
                af[mi][3] = *(const unsigned*)&as_[rb + 8][kc + 8];
            }
#pragma unroll
            for (int nj = 0; nj < 4; nj++) {
                int bn = nw + nj * 8 + r0;
                unsigned bf[2];
                bf[0] = *(const unsigned*)&ws[bn][kc];
                bf[1] = *(const unsigned*)&ws[bn][kc + 8];
                mma16816(acc[0][nj], af[0], bf);
                mma16816(acc[1][nj], af[1], bf);
            }
        }
        __syncthreads();
    }
    // epilogue: scale by routing weight, write y
#pragma unroll
    for (int mi = 0; mi < 2; mi++) {
#pragma unroll
        for (int nj = 0; nj < 4; nj++) {
            int row = mw + mi * 16 + (lane >> 2);
            int col = n0 + nw + nj * 8 + (lane & 3) * 2;
            int m0r = m0 + row;
            if (m0r < cnt) {
                float wc = g_wt[e * T_ + m0r];
                float* yp = g_y + (e * T_ + m0r) * D_ + col;
                yp[0] = acc[mi][nj][0] * wc;
                yp[1] = acc[mi][nj][1] * wc;
            }
            if (m0r + 8 < cnt) {
                float wc = g_wt[e * T_ + m0r + 8];
                float* yp = g_y + (e * T_ + m0r + 8) * D_ + col;
                yp[0] = acc[mi][nj][2] * wc;
                yp[1] = acc[mi][nj][3] * wc;
            }
        }
    }
}

// ---------------- 5) combine: out[t,d] = sum_e y[e, slot(t,e), d] -----------
__global__ __launch_bounds__(256) void k_combine(float* __restrict__ out) {
    int t = blockIdx.x;
    __shared__ int sl[E_];
    if (threadIdx.x < E_) sl[threadIdx.x] = g_slot[t * E_ + threadIdx.x];
    __syncthreads();
    for (int d = threadIdx.x; d < D_; d += 256) {
        float acc = 0.f;
#pragma unroll
        for (int e = 0; e < E_; e++) {
            int s = sl[e];
            if (s >= 0) acc += g_y[(e * T_ + s) * D_ + d];
        }
        out[t * D_ + d] = acc;
    }
}

// ---------------- launch -----------------------------------------------------
extern "C" void kernel_launch(void* const* d_in, const int* in_sizes, int n_in,
                              void* d_out, int out_size) {
    const float* x    = (const float*)d_in[0];
    const float* tw   = (const float*)d_in[1];
    const int*   tids = (const int*)d_in[2];
    const int*   w13  = (const int*)d_in[3];
    const int*   w13s = (const int*)d_in[4];
    const int*   w2   = (const int*)d_in[5];
    const int*   w2s  = (const int*)d_in[6];
    float* out = (float*)d_out;

    k_quant<<<(T_ * D_ / 32) / 8, 256>>>(x);
    k_route<<<1, 512>>>(tw, tids);
    k_gemm1<<<dim3(H2_ / 128, T_ / 64, E_), 256>>>(w13, w13s);
    k_act<<<dim3(T_, E_), 256>>>();
    k_gemm2<<<dim3(D_ / 128, T_ / 64, E_), 256>>>(w2, w2s);
    k_combine<<<T_, 256>>>(out);
}